// round 11
// baseline (speedup 1.0000x reference)
#include <cuda_runtime.h>
#include <cuda_bf16.h>
#include <cstdint>
#include <cstddef>

// ---------------------------------------------------------------------------
// Problem: B=4, L=2048, D=1024, H=16, Hd=64
//   qkv = x @ W_attn + b_attn            [8192 x 3072]
//   attn (causal, 16 heads, softmax)      -> o [8192 x 1024]
//   out = o @ W_proj + b_proj             [8192 x 1024]
// Round 10: GEMM mainloop restructured: KCH=16, 3-stage cp.async pipeline,
// prefetch at top of iteration, ONE barrier per iteration. Attention
// unchanged from round 9 (bf16 mma.sync hi/lo 3-pass).
// tcgen05 unusable: harness PTX targets sm_103 (no 'a' feature set).
// ---------------------------------------------------------------------------

#define Bq 4
#define Lq 2048
#define Hq 16
#define HDq 64

// bf16 split scratch
__device__ __nv_bfloat16 g_ahi[8192 * 1024];   // x / o (hi)
__device__ __nv_bfloat16 g_alo[8192 * 1024];   // x / o (lo)
__device__ __nv_bfloat16 g_wahi[3072 * 1024];  // W_attn^T split
__device__ __nv_bfloat16 g_walo[3072 * 1024];
__device__ __nv_bfloat16 g_wphi[1024 * 1024];  // W_proj^T split
__device__ __nv_bfloat16 g_wplo[1024 * 1024];
// qkv bf16 hi/lo; q pre-scaled by 0.125; v stored TRANSPOSED [b,h,d,l]
__device__ __nv_bfloat16 g_qhi[64 * 2048 * 64];
__device__ __nv_bfloat16 g_qlo[64 * 2048 * 64];
__device__ __nv_bfloat16 g_khi[64 * 2048 * 64];
__device__ __nv_bfloat16 g_klo[64 * 2048 * 64];
__device__ __nv_bfloat16 g_vhi[64 * 64 * 2048];
__device__ __nv_bfloat16 g_vlo[64 * 64 * 2048];

__device__ __forceinline__ uint32_t smem_to_u32(const void* p) {
    uint32_t a;
    asm("{ .reg .u64 t; cvta.to.shared.u64 t, %1; cvt.u32.u64 %0, t; }"
        : "=r"(a) : "l"(p));
    return a;
}

#define LDMATRIX_X4(r0, r1, r2, r3, addr) \
    asm volatile("ldmatrix.sync.aligned.m8n8.x4.shared.b16 {%0,%1,%2,%3}, [%4];" \
                 : "=r"(r0), "=r"(r1), "=r"(r2), "=r"(r3) : "r"(addr))

#define MMA_BF16(c, a, b) \
    asm volatile( \
        "mma.sync.aligned.m16n8k16.row.col.f32.bf16.bf16.f32 " \
        "{%0,%1,%2,%3}, {%4,%5,%6,%7}, {%8,%9}, {%0,%1,%2,%3};" \
        : "+f"((c)[0]), "+f"((c)[1]), "+f"((c)[2]), "+f"((c)[3]) \
        : "r"((a)[0]), "r"((a)[1]), "r"((a)[2]), "r"((a)[3]), \
          "r"((b)[0]), "r"((b)[1]))

#define CP_ASYNC16(dst, src) \
    asm volatile("cp.async.cg.shared.global [%0], [%1], 16;" \
                 :: "r"(dst), "l"(src))
#define CP_COMMIT() asm volatile("cp.async.commit_group;" ::: "memory")
#define CP_WAIT0() asm volatile("cp.async.wait_group 0;" ::: "memory")
#define CP_WAIT1() asm volatile("cp.async.wait_group 1;" ::: "memory")

// pack two floats -> bf16x2 (lo = first arg), plus residual split
__device__ __forceinline__ uint32_t cvt_bf162(float lo, float hi) {
    uint32_t r;
    asm("cvt.rn.bf16x2.f32 %0, %1, %2;" : "=r"(r) : "f"(hi), "f"(lo));
    return r;
}
__device__ __forceinline__ void split2(float x, float y, uint32_t& h, uint32_t& l) {
    h = cvt_bf162(x, y);
    float xr = x - __int_as_float(h << 16);
    float yr = y - __int_as_float(h & 0xFFFF0000u);
    l = cvt_bf162(xr, yr);
}

// ---------------------------------------------------------------------------
// Split kernels: fp32 -> bf16 hi + bf16 lo
// ---------------------------------------------------------------------------
__global__ void split_kernel(const float* __restrict__ in,
                             __nv_bfloat16* __restrict__ hi,
                             __nv_bfloat16* __restrict__ lo, int n) {
    int i = (blockIdx.x * blockDim.x + threadIdx.x) * 4;
    if (i >= n) return;
    float4 v = *(const float4*)(in + i);
    uint32_t h0, l0, h1, l1;
    split2(v.x, v.y, h0, l0);
    split2(v.z, v.w, h1, l1);
    *(uint32_t*)(hi + i) = h0;
    *(uint32_t*)(hi + i + 2) = h1;
    *(uint32_t*)(lo + i) = l0;
    *(uint32_t*)(lo + i + 2) = l1;
}

// W [1024, Ncols] -> Wt hi/lo [Ncols, 1024]  (transpose + split)
__global__ void wsplit_kernel(const float* __restrict__ W,
                              __nv_bfloat16* __restrict__ hi,
                              __nv_bfloat16* __restrict__ lo, int Ncols) {
    __shared__ float t[32][33];
    int n0 = blockIdx.x * 32, k0 = blockIdx.y * 32;
    int tx = threadIdx.x & 31, ty = threadIdx.x >> 5;  // 32 x 8
    #pragma unroll
    for (int r = 0; r < 32; r += 8)
        t[ty + r][tx] = W[(size_t)(k0 + ty + r) * Ncols + n0 + tx];
    __syncthreads();
    #pragma unroll
    for (int r = 0; r < 32; r += 8) {
        float v = t[tx][ty + r];  // W[k0+tx][n0+ty+r]
        __nv_bfloat16 h = __float2bfloat16(v);
        size_t di = (size_t)(n0 + ty + r) * 1024 + k0 + tx;
        hi[di] = h;
        lo[di] = __float2bfloat16(v - __bfloat162float(h));
    }
}

// ---------------------------------------------------------------------------
// mma.sync GEMM: C[M,N] = Asplit[M,1024] @ Bsplit[N,1024]^T + bias
// 128x128 CTA tile, 8 warps (2x4 -> 64x32 warp tile), Kc=16 chunks (64 iters),
// 3-stage cp.async pipeline, prefetch at top, ONE barrier per iteration.
// Rows padded to 48B (conflict-free ldmatrix: r*48 mod 128 all distinct).
// mode 0: row-major fp32 C store.
// mode 1: qkv epilogue -> bf16 hi/lo arrays (q scaled 0.125; v transposed).
// ---------------------------------------------------------------------------
#define NCH 64                         // 1024 / 16
#define T6 6144                        // 128 rows x 48B per tile
#define STAGEB (4 * T6)                // Ahi, Alo, Bhi, Blo = 24576
#define GEMM_SMEM (3 * STAGEB)         // 73728

__global__ __launch_bounds__(256, 2)
void mma_gemm(const __nv_bfloat16* __restrict__ Ahi,
              const __nv_bfloat16* __restrict__ Alo,
              const __nv_bfloat16* __restrict__ Bhi,
              const __nv_bfloat16* __restrict__ Blo,
              const float* __restrict__ bias, float* __restrict__ C, int N,
              int mode,
              __nv_bfloat16* __restrict__ qh_, __nv_bfloat16* __restrict__ ql_,
              __nv_bfloat16* __restrict__ kh_, __nv_bfloat16* __restrict__ kl_,
              __nv_bfloat16* __restrict__ vh_, __nv_bfloat16* __restrict__ vl_) {
    extern __shared__ __align__(128) char smem[];
    const uint32_t smem_u32 = smem_to_u32(smem);
    const int tid = threadIdx.x;
    const int wid = tid >> 5;
    const int lane = tid & 31;
    const int wm = wid >> 2;
    const int wn = wid & 3;
    const int bn = blockIdx.x * 128;
    const int bm = blockIdx.y * 128;

    float acc[4][4][4];
    #pragma unroll
    for (int mt = 0; mt < 4; mt++)
        #pragma unroll
        for (int nt = 0; nt < 4; nt++)
            #pragma unroll
            for (int r = 0; r < 4; r++) acc[mt][nt][r] = 0.0f;

    // 16-col chunk loader: per tile, 128 rows x 2 x 16B chunks = 256 cp.async
    const int lrow = tid >> 1;          // 0..127
    const int lc = tid & 1;             // 0,1
    auto load_stage = [&](int kc, int stage) {
        const int k0 = kc * 16;
        const uint32_t sb = smem_u32 + stage * STAGEB;
        const uint32_t doff = lrow * 48 + lc * 16;
        const size_t goff = (size_t)lrow * 1024 + k0 + lc * 8;
        CP_ASYNC16(sb + doff,          Ahi + (size_t)bm * 1024 + goff);
        CP_ASYNC16(sb + T6 + doff,     Alo + (size_t)bm * 1024 + goff);
        CP_ASYNC16(sb + 2 * T6 + doff, Bhi + (size_t)bn * 1024 + goff);
        CP_ASYNC16(sb + 3 * T6 + doff, Blo + (size_t)bn * 1024 + goff);
        CP_COMMIT();
    };

    load_stage(0, 0);
    load_stage(1, 1);

    const int amat = lane >> 3;
    const int rowin = lane & 7;
    const int am_base = wm * 64 + (amat & 1) * 8 + rowin;
    const int ak16 = (amat >> 1) * 16;                 // byte offset of k-half
    const int bn_base = wn * 32 + ((lane >> 3) >> 1) * 8 + rowin;
    const int bk16 = ((lane >> 3) & 1) * 16;

    int st = 0;  // kc % 3
    for (int kc = 0; kc < NCH; kc++) {
        if (kc + 1 < NCH) CP_WAIT1(); else CP_WAIT0();
        __syncthreads();

        // prefetch kc+2 into the stage freed at kc-1 (distinct from kc, kc+1)
        int pst = st + 2; if (pst >= 3) pst -= 3;
        if (kc + 2 < NCH) load_stage(kc + 2, pst);

        const uint32_t sb = smem_u32 + st * STAGEB;
        uint32_t ah[4][4], al[4][4], bh[4][2], bl[4][2];
        #pragma unroll
        for (int mt = 0; mt < 4; mt++) {
            uint32_t a = sb + (am_base + mt * 16) * 48 + ak16;
            LDMATRIX_X4(ah[mt][0], ah[mt][1], ah[mt][2], ah[mt][3], a);
            LDMATRIX_X4(al[mt][0], al[mt][1], al[mt][2], al[mt][3], a + T6);
        }
        #pragma unroll
        for (int np = 0; np < 2; np++) {
            uint32_t b = sb + 2 * T6 + (bn_base + np * 16) * 48 + bk16;
            LDMATRIX_X4(bh[np * 2][0], bh[np * 2][1],
                        bh[np * 2 + 1][0], bh[np * 2 + 1][1], b);
            LDMATRIX_X4(bl[np * 2][0], bl[np * 2][1],
                        bl[np * 2 + 1][0], bl[np * 2 + 1][1], b + T6);
        }
        #pragma unroll
        for (int mt = 0; mt < 4; mt++)
            #pragma unroll
            for (int nt = 0; nt < 4; nt++) {
                MMA_BF16(acc[mt][nt], ah[mt], bh[nt]);
                MMA_BF16(acc[mt][nt], ah[mt], bl[nt]);
                MMA_BF16(acc[mt][nt], al[mt], bh[nt]);
            }

        if (++st == 3) st = 0;
    }

    // ---- epilogue
    const int mrow = lane >> 2;
    const int ncol = (lane & 3) * 2;
    #pragma unroll
    for (int mt = 0; mt < 4; mt++) {
        #pragma unroll
        for (int nt = 0; nt < 4; nt++) {
            int n = bn + wn * 32 + nt * 8 + ncol;
            float2 bv = *(const float2*)(bias + n);
            #pragma unroll
            for (int half = 0; half < 2; half++) {
                int m = bm + wm * 64 + mt * 16 + mrow + half * 8;
                float2 v;
                v.x = acc[mt][nt][half * 2 + 0] + bv.x;
                v.y = acc[mt][nt][half * 2 + 1] + bv.y;
                if (mode == 0) {
                    *(float2*)(C + (size_t)m * N + n) = v;
                } else {
                    int which = n >> 10;
                    int rem = n & 1023;
                    int h = rem >> 6;
                    int d = rem & 63;
                    int b = m >> 11;
                    int l = m & 2047;
                    int bh = b * Hq + h;
                    if (which == 0) {
                        uint32_t h2, l2;
                        split2(v.x * 0.125f, v.y * 0.125f, h2, l2);
                        size_t di = ((size_t)bh * Lq + l) * HDq + d;
                        *(uint32_t*)(qh_ + di) = h2;
                        *(uint32_t*)(ql_ + di) = l2;
                    } else if (which == 1) {
                        uint32_t h2, l2;
                        split2(v.x, v.y, h2, l2);
                        size_t di = ((size_t)bh * Lq + l) * HDq + d;
                        *(uint32_t*)(kh_ + di) = h2;
                        *(uint32_t*)(kl_ + di) = l2;
                    } else {
                        // v transposed: [bh][d][l]
                        size_t base = ((size_t)bh * HDq + d) * Lq + l;
                        __nv_bfloat16 h0 = __float2bfloat16(v.x);
                        vh_[base] = h0;
                        vl_[base] = __float2bfloat16(v.x - __bfloat162float(h0));
                        __nv_bfloat16 h1 = __float2bfloat16(v.y);
                        vh_[base + Lq] = h1;
                        vl_[base + Lq] = __float2bfloat16(v.y - __bfloat162float(h1));
                    }
                }
            }
        }
    }
}

// ---------------------------------------------------------------------------
// Flash attention (causal) on mma.sync bf16, 3-pass hi/lo for S and PV.
// (unchanged from round 9)
// ---------------------------------------------------------------------------
#define AROWB 144
#define ATTN_SMEM 110592

__global__ __launch_bounds__(256, 2)
void attn_mma(const __nv_bfloat16* __restrict__ qhi,
              const __nv_bfloat16* __restrict__ qlo,
              const __nv_bfloat16* __restrict__ khi,
              const __nv_bfloat16* __restrict__ klo,
              const __nv_bfloat16* __restrict__ vhi,
              const __nv_bfloat16* __restrict__ vlo,
              __nv_bfloat16* __restrict__ ohi,
              __nv_bfloat16* __restrict__ olo) {
    extern __shared__ __align__(128) char smem[];
    const uint32_t su = smem_to_u32(smem);
    const int bh = blockIdx.y;
    const int qt = (int)gridDim.x - 1 - blockIdx.x;   // heavy tiles first
    const int q0 = qt * 128;
    const int tid = threadIdx.x;
    const int wid = tid >> 5;
    const int lane = tid & 31;
    const int r0 = wid * 16;
    const int rowin = lane & 7;
    const int g1 = (lane >> 3) & 1;
    const int g2 = (lane >> 3) >> 1;

    auto load_kv = [&](int kt2, int st) {
        const int k0 = kt2 * 64;
        const uint32_t sb = su + 36864 + st * 36864;
        #pragma unroll
        for (int s = 0; s < 2; s++) {
            int idx = s * 256 + tid;
            int row = idx >> 3;
            int c = idx & 7;
            const __nv_bfloat16* gk = khi + ((size_t)bh * Lq + k0 + row) * HDq + c * 8;
            CP_ASYNC16(sb + row * AROWB + c * 16, gk);
            const __nv_bfloat16* gk2 = klo + ((size_t)bh * Lq + k0 + row) * HDq + c * 8;
            CP_ASYNC16(sb + 9216 + row * AROWB + c * 16, gk2);
            const __nv_bfloat16* gv = vhi + ((size_t)bh * HDq + row) * Lq + k0 + c * 8;
            CP_ASYNC16(sb + 18432 + row * AROWB + c * 16, gv);
            const __nv_bfloat16* gv2 = vlo + ((size_t)bh * HDq + row) * Lq + k0 + c * 8;
            CP_ASYNC16(sb + 27648 + row * AROWB + c * 16, gv2);
        }
        CP_COMMIT();
    };

    #pragma unroll
    for (int s = 0; s < 4; s++) {
        int idx = s * 256 + tid;
        int row = idx >> 3;
        int c = idx & 7;
        const __nv_bfloat16* gq = qhi + ((size_t)bh * Lq + q0 + row) * HDq + c * 8;
        CP_ASYNC16(su + row * AROWB + c * 16, gq);
        const __nv_bfloat16* gq2 = qlo + ((size_t)bh * Lq + q0 + row) * HDq + c * 8;
        CP_ASYNC16(su + 18432 + row * AROWB + c * 16, gq2);
    }
    load_kv(0, 0);
    load_kv(1, 1);

    float oacc[8][4];
    #pragma unroll
    for (int nt = 0; nt < 8; nt++)
        #pragma unroll
        for (int r = 0; r < 4; r++) oacc[nt][r] = 0.0f;
    float mA = -1e30f, mB = -1e30f, lA = 0.0f, lB = 0.0f;

    const int nkt = 2 * qt + 2;
    for (int kt = 0; kt < nkt; kt++) {
        if (kt + 1 < nkt) CP_WAIT1(); else CP_WAIT0();
        __syncthreads();
        const uint32_t sb = su + 36864 + (kt & 1) * 36864;
        const int k0 = kt * 64;

        float sacc[8][4];
        #pragma unroll
        for (int nt = 0; nt < 8; nt++)
            #pragma unroll
            for (int r = 0; r < 4; r++) sacc[nt][r] = 0.0f;

        #pragma unroll
        for (int kk = 0; kk < 4; kk++) {
            uint32_t qhf[4], qlf[4];
            uint32_t qa = su + (r0 + g1 * 8 + rowin) * AROWB + (kk * 16 + g2 * 8) * 2;
            LDMATRIX_X4(qhf[0], qhf[1], qhf[2], qhf[3], qa);
            LDMATRIX_X4(qlf[0], qlf[1], qlf[2], qlf[3], qa + 18432);
            #pragma unroll
            for (int np = 0; np < 4; np++) {
                uint32_t kbh[2][2], kbl[2][2];
                uint32_t ka = sb + (np * 16 + g2 * 8 + rowin) * AROWB +
                              (kk * 16 + g1 * 8) * 2;
                LDMATRIX_X4(kbh[0][0], kbh[0][1], kbh[1][0], kbh[1][1], ka);
                LDMATRIX_X4(kbl[0][0], kbl[0][1], kbl[1][0], kbl[1][1], ka + 9216);
                MMA_BF16(sacc[np * 2], qhf, kbh[0]);
                MMA_BF16(sacc[np * 2], qhf, kbl[0]);
                MMA_BF16(sacc[np * 2], qlf, kbh[0]);
                MMA_BF16(sacc[np * 2 + 1], qhf, kbh[1]);
                MMA_BF16(sacc[np * 2 + 1], qhf, kbl[1]);
                MMA_BF16(sacc[np * 2 + 1], qlf, kbh[1]);
            }
        }

        const int rA = q0 + r0 + (lane >> 2);
        if (kt >= 2 * qt) {
            #pragma unroll
            for (int nt = 0; nt < 8; nt++) {
                int c0 = k0 + nt * 8 + (lane & 3) * 2;
                if (c0 > rA) sacc[nt][0] = -1e30f;
                if (c0 + 1 > rA) sacc[nt][1] = -1e30f;
                if (c0 > rA + 8) sacc[nt][2] = -1e30f;
                if (c0 + 1 > rA + 8) sacc[nt][3] = -1e30f;
            }
        }

        float mxA = -1e30f, mxB = -1e30f;
        #pragma unroll
        for (int nt = 0; nt < 8; nt++) {
            mxA = fmaxf(mxA, fmaxf(sacc[nt][0], sacc[nt][1]));
            mxB = fmaxf(mxB, fmaxf(sacc[nt][2], sacc[nt][3]));
        }
        mxA = fmaxf(mxA, __shfl_xor_sync(0xffffffffu, mxA, 1));
        mxA = fmaxf(mxA, __shfl_xor_sync(0xffffffffu, mxA, 2));
        mxB = fmaxf(mxB, __shfl_xor_sync(0xffffffffu, mxB, 1));
        mxB = fmaxf(mxB, __shfl_xor_sync(0xffffffffu, mxB, 2));
        float mnA = fmaxf(mA, mxA);
        float mnB = fmaxf(mB, mxB);
        float aA = __expf(mA - mnA);
        float aB = __expf(mB - mnB);
        mA = mnA;
        mB = mnB;
        float lsA = 0.0f, lsB = 0.0f;
        #pragma unroll
        for (int nt = 0; nt < 8; nt++) {
            float p0 = __expf(sacc[nt][0] - mA);
            float p1 = __expf(sacc[nt][1] - mA);
            float p2 = __expf(sacc[nt][2] - mB);
            float p3 = __expf(sacc[nt][3] - mB);
            sacc[nt][0] = p0; sacc[nt][1] = p1;
            sacc[nt][2] = p2; sacc[nt][3] = p3;
            lsA += p0 + p1;
            lsB += p2 + p3;
        }
        lA = lA * aA + lsA;
        lB = lB * aB + lsB;
        #pragma unroll
        for (int nt = 0; nt < 8; nt++) {
            oacc[nt][0] *= aA; oacc[nt][1] *= aA;
            oacc[nt][2] *= aB; oacc[nt][3] *= aB;
        }

        #pragma unroll
        for (int kk2 = 0; kk2 < 4; kk2++) {
            const int t0 = kk2 * 2, t1 = t0 + 1;
            uint32_t ph[4], pl[4];
            split2(sacc[t0][0], sacc[t0][1], ph[0], pl[0]);
            split2(sacc[t0][2], sacc[t0][3], ph[1], pl[1]);
            split2(sacc[t1][0], sacc[t1][1], ph[2], pl[2]);
            split2(sacc[t1][2], sacc[t1][3], ph[3], pl[3]);
            #pragma unroll
            for (int np = 0; np < 4; np++) {
                uint32_t vbh[2][2], vbl[2][2];
                uint32_t va = sb + 18432 + (np * 16 + g2 * 8 + rowin) * AROWB +
                              (kk2 * 16 + g1 * 8) * 2;
                LDMATRIX_X4(vbh[0][0], vbh[0][1], vbh[1][0], vbh[1][1], va);
                LDMATRIX_X4(vbl[0][0], vbl[0][1], vbl[1][0], vbl[1][1], va + 9216);
                MMA_BF16(oacc[np * 2], ph, vbh[0]);
                MMA_BF16(oacc[np * 2], ph, vbl[0]);
                MMA_BF16(oacc[np * 2], pl, vbh[0]);
                MMA_BF16(oacc[np * 2 + 1], ph, vbh[1]);
                MMA_BF16(oacc[np * 2 + 1], ph, vbl[1]);
                MMA_BF16(oacc[np * 2 + 1], pl, vbh[1]);
            }
        }

        __syncthreads();
        if (kt + 2 < nkt) load_kv(kt + 2, kt & 1);
    }

    lA += __shfl_xor_sync(0xffffffffu, lA, 1);
    lA += __shfl_xor_sync(0xffffffffu, lA, 2);
    lB += __shfl_xor_sync(0xffffffffu, lB, 1);
    lB += __shfl_xor_sync(0xffffffffu, lB, 2);
    float iA = 1.0f / lA;
    float iB = 1.0f / lB;

    const int b = bh >> 4;
    const int hh = bh & 15;
    const int rgA = q0 + r0 + (lane >> 2);
    #pragma unroll
    for (int nt = 0; nt < 8; nt++) {
        int d = nt * 8 + (lane & 3) * 2;
        size_t ia = ((size_t)(b * Lq + rgA)) * 1024 + hh * 64 + d;
        size_t ib = ((size_t)(b * Lq + rgA + 8)) * 1024 + hh * 64 + d;
        uint32_t h2, l2;
        split2(oacc[nt][0] * iA, oacc[nt][1] * iA, h2, l2);
        *(uint32_t*)(ohi + ia) = h2;
        *(uint32_t*)(olo + ia) = l2;
        split2(oacc[nt][2] * iB, oacc[nt][3] * iB, h2, l2);
        *(uint32_t*)(ohi + ib) = h2;
        *(uint32_t*)(olo + ib) = l2;
    }
}

// ---------------------------------------------------------------------------
// Launch
// ---------------------------------------------------------------------------
extern "C" void kernel_launch(void* const* d_in, const int* in_sizes, int n_in,
                              void* d_out, int out_size) {
    const float* x  = (const float*)d_in[0];
    const float* Wa = (const float*)d_in[1];
    const float* ba = (const float*)d_in[2];
    const float* Wp = (const float*)d_in[3];
    const float* bp = (const float*)d_in[4];
    float* out = (float*)d_out;

    __nv_bfloat16 *ahi, *alo, *wahi, *walo, *wphi, *wplo;
    __nv_bfloat16 *qhi, *qlo, *khi, *klo, *vhi, *vlo;
    cudaGetSymbolAddress((void**)&ahi, g_ahi);
    cudaGetSymbolAddress((void**)&alo, g_alo);
    cudaGetSymbolAddress((void**)&wahi, g_wahi);
    cudaGetSymbolAddress((void**)&walo, g_walo);
    cudaGetSymbolAddress((void**)&wphi, g_wphi);
    cudaGetSymbolAddress((void**)&wplo, g_wplo);
    cudaGetSymbolAddress((void**)&qhi, g_qhi);
    cudaGetSymbolAddress((void**)&qlo, g_qlo);
    cudaGetSymbolAddress((void**)&khi, g_khi);
    cudaGetSymbolAddress((void**)&klo, g_klo);
    cudaGetSymbolAddress((void**)&vhi, g_vhi);
    cudaGetSymbolAddress((void**)&vlo, g_vlo);

    cudaFuncSetAttribute(mma_gemm, cudaFuncAttributeMaxDynamicSharedMemorySize,
                         GEMM_SMEM);
    cudaFuncSetAttribute(attn_mma, cudaFuncAttributeMaxDynamicSharedMemorySize,
                         ATTN_SMEM);

    // Split inputs to bf16 hi/lo
    split_kernel<<<8192, 256>>>(x, ahi, alo, 8192 * 1024);
    wsplit_kernel<<<dim3(96, 32), 256>>>(Wa, wahi, walo, 3072);
    wsplit_kernel<<<dim3(32, 32), 256>>>(Wp, wphi, wplo, 1024);

    // 1) QKV projection -> bf16 hi/lo q(scaled)/k/v(transposed)
    mma_gemm<<<dim3(24, 64), 256, GEMM_SMEM>>>(
        ahi, alo, wahi, walo, ba, nullptr, 3072, 1,
        qhi, qlo, khi, klo, vhi, vlo);

    // 2) causal flash attention (tensor cores) -> o hi/lo into ahi/alo
    attn_mma<<<dim3(16, 64), 256, ATTN_SMEM>>>(qhi, qlo, khi, klo, vhi, vlo,
                                               ahi, alo);

    // 3) output projection
    mma_gemm<<<dim3(8, 64), 256, GEMM_SMEM>>>(
        ahi, alo, wphi, wplo, bp, out, 1024, 0,
        nullptr, nullptr, nullptr, nullptr, nullptr, nullptr);
}

// round 13
// speedup vs baseline: 1.0605x; 1.0605x over previous
#include <cuda_runtime.h>
#include <cuda_bf16.h>
#include <cstdint>
#include <cstddef>

// ---------------------------------------------------------------------------
// Problem: B=4, L=2048, D=1024, H=16, Hd=64
//   qkv = x @ W_attn + b_attn            [8192 x 3072]
//   attn (causal, 16 heads, softmax)      -> o [8192 x 1024]
//   out = o @ W_proj + b_proj             [8192 x 1024]
// Round 13 = resubmit of round 11 (infra failed twice, never measured):
// R9 GEMM config (KCH=32, 2-stage, 2 CTA/SM) + pass-major MMA ordering
// (same-accumulator distance 1 -> 16) to break HMMA RAW chains; same
// interleave in attention S/PV triples.
// tcgen05 unusable: harness PTX targets sm_103 (no 'a' feature set).
// ---------------------------------------------------------------------------

#define Bq 4
#define Lq 2048
#define Hq 16
#define HDq 64

// bf16 split scratch
__device__ __nv_bfloat16 g_ahi[8192 * 1024];   // x / o (hi)
__device__ __nv_bfloat16 g_alo[8192 * 1024];   // x / o (lo)
__device__ __nv_bfloat16 g_wahi[3072 * 1024];  // W_attn^T split
__device__ __nv_bfloat16 g_walo[3072 * 1024];
__device__ __nv_bfloat16 g_wphi[1024 * 1024];  // W_proj^T split
__device__ __nv_bfloat16 g_wplo[1024 * 1024];
// qkv bf16 hi/lo; q pre-scaled by 0.125; v stored TRANSPOSED [b,h,d,l]
__device__ __nv_bfloat16 g_qhi[64 * 2048 * 64];
__device__ __nv_bfloat16 g_qlo[64 * 2048 * 64];
__device__ __nv_bfloat16 g_khi[64 * 2048 * 64];
__device__ __nv_bfloat16 g_klo[64 * 2048 * 64];
__device__ __nv_bfloat16 g_vhi[64 * 64 * 2048];
__device__ __nv_bfloat16 g_vlo[64 * 64 * 2048];

__device__ __forceinline__ uint32_t smem_to_u32(const void* p) {
    uint32_t a;
    asm("{ .reg .u64 t; cvta.to.shared.u64 t, %1; cvt.u32.u64 %0, t; }"
        : "=r"(a) : "l"(p));
    return a;
}

#define LDMATRIX_X4(r0, r1, r2, r3, addr) \
    asm volatile("ldmatrix.sync.aligned.m8n8.x4.shared.b16 {%0,%1,%2,%3}, [%4];" \
                 : "=r"(r0), "=r"(r1), "=r"(r2), "=r"(r3) : "r"(addr))

#define MMA_BF16(c, a, b) \
    asm volatile( \
        "mma.sync.aligned.m16n8k16.row.col.f32.bf16.bf16.f32 " \
        "{%0,%1,%2,%3}, {%4,%5,%6,%7}, {%8,%9}, {%0,%1,%2,%3};" \
        : "+f"((c)[0]), "+f"((c)[1]), "+f"((c)[2]), "+f"((c)[3]) \
        : "r"((a)[0]), "r"((a)[1]), "r"((a)[2]), "r"((a)[3]), \
          "r"((b)[0]), "r"((b)[1]))

#define CP_ASYNC16(dst, src) \
    asm volatile("cp.async.cg.shared.global [%0], [%1], 16;" \
                 :: "r"(dst), "l"(src))
#define CP_COMMIT() asm volatile("cp.async.commit_group;" ::: "memory")
#define CP_WAIT0() asm volatile("cp.async.wait_group 0;" ::: "memory")
#define CP_WAIT1() asm volatile("cp.async.wait_group 1;" ::: "memory")

// pack two floats -> bf16x2 (lo = first arg), plus residual split
__device__ __forceinline__ uint32_t cvt_bf162(float lo, float hi) {
    uint32_t r;
    asm("cvt.rn.bf16x2.f32 %0, %1, %2;" : "=r"(r) : "f"(hi), "f"(lo));
    return r;
}
__device__ __forceinline__ void split2(float x, float y, uint32_t& h, uint32_t& l) {
    h = cvt_bf162(x, y);
    float xr = x - __int_as_float(h << 16);
    float yr = y - __int_as_float(h & 0xFFFF0000u);
    l = cvt_bf162(xr, yr);
}

// ---------------------------------------------------------------------------
// Split kernels: fp32 -> bf16 hi + bf16 lo
// ---------------------------------------------------------------------------
__global__ void split_kernel(const float* __restrict__ in,
                             __nv_bfloat16* __restrict__ hi,
                             __nv_bfloat16* __restrict__ lo, int n) {
    int i = (blockIdx.x * blockDim.x + threadIdx.x) * 4;
    if (i >= n) return;
    float4 v = *(const float4*)(in + i);
    uint32_t h0, l0, h1, l1;
    split2(v.x, v.y, h0, l0);
    split2(v.z, v.w, h1, l1);
    *(uint32_t*)(hi + i) = h0;
    *(uint32_t*)(hi + i + 2) = h1;
    *(uint32_t*)(lo + i) = l0;
    *(uint32_t*)(lo + i + 2) = l1;
}

// W [1024, Ncols] -> Wt hi/lo [Ncols, 1024]  (transpose + split)
__global__ void wsplit_kernel(const float* __restrict__ W,
                              __nv_bfloat16* __restrict__ hi,
                              __nv_bfloat16* __restrict__ lo, int Ncols) {
    __shared__ float t[32][33];
    int n0 = blockIdx.x * 32, k0 = blockIdx.y * 32;
    int tx = threadIdx.x & 31, ty = threadIdx.x >> 5;  // 32 x 8
    #pragma unroll
    for (int r = 0; r < 32; r += 8)
        t[ty + r][tx] = W[(size_t)(k0 + ty + r) * Ncols + n0 + tx];
    __syncthreads();
    #pragma unroll
    for (int r = 0; r < 32; r += 8) {
        float v = t[tx][ty + r];  // W[k0+tx][n0+ty+r]
        __nv_bfloat16 h = __float2bfloat16(v);
        size_t di = (size_t)(n0 + ty + r) * 1024 + k0 + tx;
        hi[di] = h;
        lo[di] = __float2bfloat16(v - __bfloat162float(h));
    }
}

// ---------------------------------------------------------------------------
// mma.sync GEMM: C[M,N] = Asplit[M,1024] @ Bsplit[N,1024]^T + bias
// 128x128 CTA tile, 8 warps (2x4 -> 64x32 warp tile), Kc=32 chunks,
// 2-stage cp.async pipeline (2 CTAs/SM), hi/lo 3-pass accumulation,
// PASS-MAJOR MMA ordering (breaks same-acc RAW chains).
// mode 0: row-major fp32 C store.
// mode 1: qkv epilogue -> bf16 hi/lo arrays (q scaled 0.125; v transposed).
// ---------------------------------------------------------------------------
#define KCH 32
#define NCHUNK 32
#define ROWP 40                        // padded row in bf16 (80B = 5x16B)
#define TILEB (128 * ROWP * 2)         // 10240 bytes per tile
#define STAGEB (4 * TILEB)             // Ahi, Alo, Bhi, Blo
#define GEMM_SMEM (2 * STAGEB)         // 81920

__global__ __launch_bounds__(256, 2)
void mma_gemm(const __nv_bfloat16* __restrict__ Ahi,
              const __nv_bfloat16* __restrict__ Alo,
              const __nv_bfloat16* __restrict__ Bhi,
              const __nv_bfloat16* __restrict__ Blo,
              const float* __restrict__ bias, float* __restrict__ C, int N,
              int mode,
              __nv_bfloat16* __restrict__ qh_, __nv_bfloat16* __restrict__ ql_,
              __nv_bfloat16* __restrict__ kh_, __nv_bfloat16* __restrict__ kl_,
              __nv_bfloat16* __restrict__ vh_, __nv_bfloat16* __restrict__ vl_) {
    extern __shared__ __align__(128) char smem[];
    const uint32_t smem_u32 = smem_to_u32(smem);
    const int tid = threadIdx.x;
    const int wid = tid >> 5;
    const int lane = tid & 31;
    const int wm = wid >> 2;
    const int wn = wid & 3;
    const int bn = blockIdx.x * 128;
    const int bm = blockIdx.y * 128;

    float acc[4][4][4];
    #pragma unroll
    for (int mt = 0; mt < 4; mt++)
        #pragma unroll
        for (int nt = 0; nt < 4; nt++)
            #pragma unroll
            for (int r = 0; r < 4; r++) acc[mt][nt][r] = 0.0f;

    auto load_stage = [&](int kc, int stage) {
        const int k0 = kc * KCH;
        const uint32_t sb = smem_u32 + stage * STAGEB;
        #pragma unroll
        for (int t = 0; t < 4; t++) {
            const __nv_bfloat16* src =
                (t == 0) ? Ahi : (t == 1) ? Alo : (t == 2) ? Bhi : Blo;
            const int rbase = (t < 2) ? bm : bn;
            #pragma unroll
            for (int s = 0; s < 2; s++) {
                int idx = s * 256 + tid;
                int row = idx >> 2;
                int c4 = idx & 3;
                const void* g = src + (size_t)(rbase + row) * 1024 + k0 + c4 * 8;
                uint32_t d = sb + t * TILEB + row * 80 + c4 * 16;
                CP_ASYNC16(d, g);
            }
        }
        CP_COMMIT();
    };

    load_stage(0, 0);
    load_stage(1, 1);

    const int amat = lane >> 3;
    const int rowin = lane & 7;
    const int am_base = wm * 64 + (amat & 1) * 8 + rowin;
    const int ak_base = (amat >> 1) * 8;
    const int bn_base = wn * 32 + ((lane >> 3) >> 1) * 8 + rowin;
    const int bk_base = ((lane >> 3) & 1) * 8;

    for (int kc = 0; kc < NCHUNK; kc++) {
        if (kc + 1 < NCHUNK) CP_WAIT1(); else CP_WAIT0();
        __syncthreads();

        const uint32_t sb = smem_u32 + (kc & 1) * STAGEB;
        #pragma unroll
        for (int ks = 0; ks < 2; ks++) {
            const int kb = ks * 16;
            uint32_t ah[4][4], al[4][4], bh[4][2], bl[4][2];
            #pragma unroll
            for (int mt = 0; mt < 4; mt++) {
                uint32_t a = sb + (am_base + mt * 16) * 80 + (ak_base + kb) * 2;
                LDMATRIX_X4(ah[mt][0], ah[mt][1], ah[mt][2], ah[mt][3], a);
                LDMATRIX_X4(al[mt][0], al[mt][1], al[mt][2], al[mt][3], a + TILEB);
            }
            #pragma unroll
            for (int np = 0; np < 2; np++) {
                uint32_t b = sb + 2 * TILEB + (bn_base + np * 16) * 80 +
                             (bk_base + kb) * 2;
                LDMATRIX_X4(bh[np * 2][0], bh[np * 2][1],
                            bh[np * 2 + 1][0], bh[np * 2 + 1][1], b);
                LDMATRIX_X4(bl[np * 2][0], bl[np * 2][1],
                            bl[np * 2 + 1][0], bl[np * 2 + 1][1], b + TILEB);
            }
            // PASS-MAJOR: same accumulator touched every 16 MMAs, not 3-in-a-row
            #pragma unroll
            for (int mt = 0; mt < 4; mt++)
                #pragma unroll
                for (int nt = 0; nt < 4; nt++)
                    MMA_BF16(acc[mt][nt], ah[mt], bh[nt]);
            #pragma unroll
            for (int mt = 0; mt < 4; mt++)
                #pragma unroll
                for (int nt = 0; nt < 4; nt++)
                    MMA_BF16(acc[mt][nt], ah[mt], bl[nt]);
            #pragma unroll
            for (int mt = 0; mt < 4; mt++)
                #pragma unroll
                for (int nt = 0; nt < 4; nt++)
                    MMA_BF16(acc[mt][nt], al[mt], bh[nt]);
        }
        __syncthreads();
        if (kc + 2 < NCHUNK) load_stage(kc + 2, kc & 1);
    }

    // ---- epilogue
    const int mrow = lane >> 2;
    const int ncol = (lane & 3) * 2;
    #pragma unroll
    for (int mt = 0; mt < 4; mt++) {
        #pragma unroll
        for (int nt = 0; nt < 4; nt++) {
            int n = bn + wn * 32 + nt * 8 + ncol;
            float2 bv = *(const float2*)(bias + n);
            #pragma unroll
            for (int half = 0; half < 2; half++) {
                int m = bm + wm * 64 + mt * 16 + mrow + half * 8;
                float2 v;
                v.x = acc[mt][nt][half * 2 + 0] + bv.x;
                v.y = acc[mt][nt][half * 2 + 1] + bv.y;
                if (mode == 0) {
                    *(float2*)(C + (size_t)m * N + n) = v;
                } else {
                    int which = n >> 10;
                    int rem = n & 1023;
                    int h = rem >> 6;
                    int d = rem & 63;
                    int b = m >> 11;
                    int l = m & 2047;
                    int bh = b * Hq + h;
                    if (which == 0) {
                        uint32_t h2, l2;
                        split2(v.x * 0.125f, v.y * 0.125f, h2, l2);
                        size_t di = ((size_t)bh * Lq + l) * HDq + d;
                        *(uint32_t*)(qh_ + di) = h2;
                        *(uint32_t*)(ql_ + di) = l2;
                    } else if (which == 1) {
                        uint32_t h2, l2;
                        split2(v.x, v.y, h2, l2);
                        size_t di = ((size_t)bh * Lq + l) * HDq + d;
                        *(uint32_t*)(kh_ + di) = h2;
                        *(uint32_t*)(kl_ + di) = l2;
                    } else {
                        // v transposed: [bh][d][l]
                        size_t base = ((size_t)bh * HDq + d) * Lq + l;
                        __nv_bfloat16 h0 = __float2bfloat16(v.x);
                        vh_[base] = h0;
                        vl_[base] = __float2bfloat16(v.x - __bfloat162float(h0));
                        __nv_bfloat16 h1 = __float2bfloat16(v.y);
                        vh_[base + Lq] = h1;
                        vl_[base + Lq] = __float2bfloat16(v.y - __bfloat162float(h1));
                    }
                }
            }
        }
    }
}

// ---------------------------------------------------------------------------
// Flash attention (causal) on mma.sync bf16, 3-pass hi/lo for S and PV.
// R9 structure; MMA triples interleaved across the two accumulators.
// ---------------------------------------------------------------------------
#define AROWB 144
#define ATTN_SMEM 110592

__global__ __launch_bounds__(256, 2)
void attn_mma(const __nv_bfloat16* __restrict__ qhi,
              const __nv_bfloat16* __restrict__ qlo,
              const __nv_bfloat16* __restrict__ khi,
              const __nv_bfloat16* __restrict__ klo,
              const __nv_bfloat16* __restrict__ vhi,
              const __nv_bfloat16* __restrict__ vlo,
              __nv_bfloat16* __restrict__ ohi,
              __nv_bfloat16* __restrict__ olo) {
    extern __shared__ __align__(128) char smem[];
    const uint32_t su = smem_to_u32(smem);
    const int bh = blockIdx.y;
    const int qt = (int)gridDim.x - 1 - blockIdx.x;   // heavy tiles first
    const int q0 = qt * 128;
    const int tid = threadIdx.x;
    const int wid = tid >> 5;
    const int lane = tid & 31;
    const int r0 = wid * 16;
    const int rowin = lane & 7;
    const int g1 = (lane >> 3) & 1;
    const int g2 = (lane >> 3) >> 1;

    auto load_kv = [&](int kt2, int st) {
        const int k0 = kt2 * 64;
        const uint32_t sb = su + 36864 + st * 36864;
        #pragma unroll
        for (int s = 0; s < 2; s++) {
            int idx = s * 256 + tid;
            int row = idx >> 3;
            int c = idx & 7;
            const __nv_bfloat16* gk = khi + ((size_t)bh * Lq + k0 + row) * HDq + c * 8;
            CP_ASYNC16(sb + row * AROWB + c * 16, gk);
            const __nv_bfloat16* gk2 = klo + ((size_t)bh * Lq + k0 + row) * HDq + c * 8;
            CP_ASYNC16(sb + 9216 + row * AROWB + c * 16, gk2);
            const __nv_bfloat16* gv = vhi + ((size_t)bh * HDq + row) * Lq + k0 + c * 8;
            CP_ASYNC16(sb + 18432 + row * AROWB + c * 16, gv);
            const __nv_bfloat16* gv2 = vlo + ((size_t)bh * HDq + row) * Lq + k0 + c * 8;
            CP_ASYNC16(sb + 27648 + row * AROWB + c * 16, gv2);
        }
        CP_COMMIT();
    };

    #pragma unroll
    for (int s = 0; s < 4; s++) {
        int idx = s * 256 + tid;
        int row = idx >> 3;
        int c = idx & 7;
        const __nv_bfloat16* gq = qhi + ((size_t)bh * Lq + q0 + row) * HDq + c * 8;
        CP_ASYNC16(su + row * AROWB + c * 16, gq);
        const __nv_bfloat16* gq2 = qlo + ((size_t)bh * Lq + q0 + row) * HDq + c * 8;
        CP_ASYNC16(su + 18432 + row * AROWB + c * 16, gq2);
    }
    load_kv(0, 0);
    load_kv(1, 1);

    float oacc[8][4];
    #pragma unroll
    for (int nt = 0; nt < 8; nt++)
        #pragma unroll
        for (int r = 0; r < 4; r++) oacc[nt][r] = 0.0f;
    float mA = -1e30f, mB = -1e30f, lA = 0.0f, lB = 0.0f;

    const int nkt = 2 * qt + 2;
    for (int kt = 0; kt < nkt; kt++) {
        if (kt + 1 < nkt) CP_WAIT1(); else CP_WAIT0();
        __syncthreads();
        const uint32_t sb = su + 36864 + (kt & 1) * 36864;
        const int k0 = kt * 64;

        float sacc[8][4];
        #pragma unroll
        for (int nt = 0; nt < 8; nt++)
            #pragma unroll
            for (int r = 0; r < 4; r++) sacc[nt][r] = 0.0f;

        #pragma unroll
        for (int kk = 0; kk < 4; kk++) {
            uint32_t qhf[4], qlf[4];
            uint32_t qa = su + (r0 + g1 * 8 + rowin) * AROWB + (kk * 16 + g2 * 8) * 2;
            LDMATRIX_X4(qhf[0], qhf[1], qhf[2], qhf[3], qa);
            LDMATRIX_X4(qlf[0], qlf[1], qlf[2], qlf[3], qa + 18432);
            #pragma unroll
            for (int np = 0; np < 4; np++) {
                uint32_t kbh[2][2], kbl[2][2];
                uint32_t ka = sb + (np * 16 + g2 * 8 + rowin) * AROWB +
                              (kk * 16 + g1 * 8) * 2;
                LDMATRIX_X4(kbh[0][0], kbh[0][1], kbh[1][0], kbh[1][1], ka);
                LDMATRIX_X4(kbl[0][0], kbl[0][1], kbl[1][0], kbl[1][1], ka + 9216);
                // interleaved: same acc every 2 MMAs (was 3-in-a-row)
                MMA_BF16(sacc[np * 2],     qhf, kbh[0]);
                MMA_BF16(sacc[np * 2 + 1], qhf, kbh[1]);
                MMA_BF16(sacc[np * 2],     qhf, kbl[0]);
                MMA_BF16(sacc[np * 2 + 1], qhf, kbl[1]);
                MMA_BF16(sacc[np * 2],     qlf, kbh[0]);
                MMA_BF16(sacc[np * 2 + 1], qlf, kbh[1]);
            }
        }

        const int rA = q0 + r0 + (lane >> 2);
        if (kt >= 2 * qt) {
            #pragma unroll
            for (int nt = 0; nt < 8; nt++) {
                int c0 = k0 + nt * 8 + (lane & 3) * 2;
                if (c0 > rA) sacc[nt][0] = -1e30f;
                if (c0 + 1 > rA) sacc[nt][1] = -1e30f;
                if (c0 > rA + 8) sacc[nt][2] = -1e30f;
                if (c0 + 1 > rA + 8) sacc[nt][3] = -1e30f;
            }
        }

        float mxA = -1e30f, mxB = -1e30f;
        #pragma unroll
        for (int nt = 0; nt < 8; nt++) {
            mxA = fmaxf(mxA, fmaxf(sacc[nt][0], sacc[nt][1]));
            mxB = fmaxf(mxB, fmaxf(sacc[nt][2], sacc[nt][3]));
        }
        mxA = fmaxf(mxA, __shfl_xor_sync(0xffffffffu, mxA, 1));
        mxA = fmaxf(mxA, __shfl_xor_sync(0xffffffffu, mxA, 2));
        mxB = fmaxf(mxB, __shfl_xor_sync(0xffffffffu, mxB, 1));
        mxB = fmaxf(mxB, __shfl_xor_sync(0xffffffffu, mxB, 2));
        float mnA = fmaxf(mA, mxA);
        float mnB = fmaxf(mB, mxB);
        float aA = __expf(mA - mnA);
        float aB = __expf(mB - mnB);
        mA = mnA;
        mB = mnB;
        float lsA = 0.0f, lsB = 0.0f;
        #pragma unroll
        for (int nt = 0; nt < 8; nt++) {
            float p0 = __expf(sacc[nt][0] - mA);
            float p1 = __expf(sacc[nt][1] - mA);
            float p2 = __expf(sacc[nt][2] - mB);
            float p3 = __expf(sacc[nt][3] - mB);
            sacc[nt][0] = p0; sacc[nt][1] = p1;
            sacc[nt][2] = p2; sacc[nt][3] = p3;
            lsA += p0 + p1;
            lsB += p2 + p3;
        }
        lA = lA * aA + lsA;
        lB = lB * aB + lsB;
        #pragma unroll
        for (int nt = 0; nt < 8; nt++) {
            oacc[nt][0] *= aA; oacc[nt][1] *= aA;
            oacc[nt][2] *= aB; oacc[nt][3] *= aB;
        }

        #pragma unroll
        for (int kk2 = 0; kk2 < 4; kk2++) {
            const int t0 = kk2 * 2, t1 = t0 + 1;
            uint32_t ph[4], pl[4];
            split2(sacc[t0][0], sacc[t0][1], ph[0], pl[0]);
            split2(sacc[t0][2], sacc[t0][3], ph[1], pl[1]);
            split2(sacc[t1][0], sacc[t1][1], ph[2], pl[2]);
            split2(sacc[t1][2], sacc[t1][3], ph[3], pl[3]);
            #pragma unroll
            for (int np = 0; np < 4; np++) {
                uint32_t vbh[2][2], vbl[2][2];
                uint32_t va = sb + 18432 + (np * 16 + g2 * 8 + rowin) * AROWB +
                              (kk2 * 16 + g1 * 8) * 2;
                LDMATRIX_X4(vbh[0][0], vbh[0][1], vbh[1][0], vbh[1][1], va);
                LDMATRIX_X4(vbl[0][0], vbl[0][1], vbl[1][0], vbl[1][1], va + 9216);
                MMA_BF16(oacc[np * 2],     ph, vbh[0]);
                MMA_BF16(oacc[np * 2 + 1], ph, vbh[1]);
                MMA_BF16(oacc[np * 2],     ph, vbl[0]);
                MMA_BF16(oacc[np * 2 + 1], ph, vbl[1]);
                MMA_BF16(oacc[np * 2],     pl, vbh[0]);
                MMA_BF16(oacc[np * 2 + 1], pl, vbh[1]);
            }
        }

        __syncthreads();
        if (kt + 2 < nkt) load_kv(kt + 2, kt & 1);
    }

    lA += __shfl_xor_sync(0xffffffffu, lA, 1);
    lA += __shfl_xor_sync(0xffffffffu, lA, 2);
    lB += __shfl_xor_sync(0xffffffffu, lB, 1);
    lB += __shfl_xor_sync(0xffffffffu, lB, 2);
    float iA = 1.0f / lA;
    float iB = 1.0f / lB;

    const int b = bh >> 4;
    const int hh = bh & 15;
    const int rgA = q0 + r0 + (lane >> 2);
    #pragma unroll
    for (int nt = 0; nt < 8; nt++) {
        int d = nt * 8 + (lane & 3) * 2;
        size_t ia = ((size_t)(b * Lq + rgA)) * 1024 + hh * 64 + d;
        size_t ib = ((size_t)(b * Lq + rgA + 8)) * 1024 + hh * 64 + d;
        uint32_t h2, l2;
        split2(oacc[nt][0] * iA, oacc[nt][1] * iA, h2, l2);
        *(uint32_t*)(ohi + ia) = h2;
        *(uint32_t*)(olo + ia) = l2;
        split2(oacc[nt][2] * iB, oacc[nt][3] * iB, h2, l2);
        *(uint32_t*)(ohi + ib) = h2;
        *(uint32_t*)(olo + ib) = l2;
    }
}

// ---------------------------------------------------------------------------
// Launch
// ---------------------------------------------------------------------------
extern "C" void kernel_launch(void* const* d_in, const int* in_sizes, int n_in,
                              void* d_out, int out_size) {
    const float* x  = (const float*)d_in[0];
    const float* Wa = (const float*)d_in[1];
    const float* ba = (const float*)d_in[2];
    const float* Wp = (const float*)d_in[3];
    const float* bp = (const float*)d_in[4];
    float* out = (float*)d_out;

    __nv_bfloat16 *ahi, *alo, *wahi, *walo, *wphi, *wplo;
    __nv_bfloat16 *qhi, *qlo, *khi, *klo, *vhi, *vlo;
    cudaGetSymbolAddress((void**)&ahi, g_ahi);
    cudaGetSymbolAddress((void**)&alo, g_alo);
    cudaGetSymbolAddress((void**)&wahi, g_wahi);
    cudaGetSymbolAddress((void**)&walo, g_walo);
    cudaGetSymbolAddress((void**)&wphi, g_wphi);
    cudaGetSymbolAddress((void**)&wplo, g_wplo);
    cudaGetSymbolAddress((void**)&qhi, g_qhi);
    cudaGetSymbolAddress((void**)&qlo, g_qlo);
    cudaGetSymbolAddress((void**)&khi, g_khi);
    cudaGetSymbolAddress((void**)&klo, g_klo);
    cudaGetSymbolAddress((void**)&vhi, g_vhi);
    cudaGetSymbolAddress((void**)&vlo, g_vlo);

    cudaFuncSetAttribute(mma_gemm, cudaFuncAttributeMaxDynamicSharedMemorySize,
                         GEMM_SMEM);
    cudaFuncSetAttribute(attn_mma, cudaFuncAttributeMaxDynamicSharedMemorySize,
                         ATTN_SMEM);

    // Split inputs to bf16 hi/lo
    split_kernel<<<8192, 256>>>(x, ahi, alo, 8192 * 1024);
    wsplit_kernel<<<dim3(96, 32), 256>>>(Wa, wahi, walo, 3072);
    wsplit_kernel<<<dim3(32, 32), 256>>>(Wp, wphi, wplo, 1024);

    // 1) QKV projection -> bf16 hi/lo q(scaled)/k/v(transposed)
    mma_gemm<<<dim3(24, 64), 256, GEMM_SMEM>>>(
        ahi, alo, wahi, walo, ba, nullptr, 3072, 1,
        qhi, qlo, khi, klo, vhi, vlo);

    // 2) causal flash attention (tensor cores) -> o hi/lo into ahi/alo
    attn_mma<<<dim3(16, 64), 256, ATTN_SMEM>>>(qhi, qlo, khi, klo, vhi, vlo,
                                               ahi, alo);

    // 3) output projection
    mma_gemm<<<dim3(8, 64), 256, GEMM_SMEM>>>(
        ahi, alo, wphi, wplo, bp, out, 1024, 0,
        nullptr, nullptr, nullptr, nullptr, nullptr, nullptr);
}

// round 16
// speedup vs baseline: 1.5283x; 1.4412x over previous
#include <cuda_runtime.h>
#include <cuda_fp16.h>
#include <cstdint>
#include <cstddef>

// ---------------------------------------------------------------------------
// Problem: B=4, L=2048, D=1024, H=16, Hd=64
//   qkv = x @ W_attn + b_attn            [8192 x 3072]
//   attn (causal, 16 heads, softmax)      -> o [8192 x 1024]
//   out = o @ W_proj + b_proj             [8192 x 1024]
// Round 14: precision scheme swap. fp16 asymmetric split:
//   A exact (fp16 hi+lo, 2-pass MMA) x B single fp16 (one rounding).
//   C = A * fl16(B): error = one fp16 rounding (u=2^-11) on one operand.
// GEMM: 2 passes (was 3), 3 smem tiles (was 4). Attention: Q,P hi/lo; K,V
// single fp16. Mainloop structure = R9 (best measured).
// tcgen05 unusable: harness PTX targets sm_103 (no 'a' feature set).
// ---------------------------------------------------------------------------

#define Bq 4
#define Lq 2048
#define Hq 16
#define HDq 64

// fp16 scratch
__device__ __half g_ahi[8192 * 1024];   // x / o (hi)
__device__ __half g_alo[8192 * 1024];   // x / o (lo)
__device__ __half g_wa[3072 * 1024];    // W_attn^T single fp16
__device__ __half g_wp[1024 * 1024];    // W_proj^T single fp16
// q hi/lo (pre-scaled 0.125); k single; v single TRANSPOSED [b,h,d,l]
__device__ __half g_qhi[64 * 2048 * 64];
__device__ __half g_qlo[64 * 2048 * 64];
__device__ __half g_k[64 * 2048 * 64];
__device__ __half g_v[64 * 64 * 2048];

__device__ __forceinline__ uint32_t smem_to_u32(const void* p) {
    uint32_t a;
    asm("{ .reg .u64 t; cvta.to.shared.u64 t, %1; cvt.u32.u64 %0, t; }"
        : "=r"(a) : "l"(p));
    return a;
}

#define LDMATRIX_X4(r0, r1, r2, r3, addr) \
    asm volatile("ldmatrix.sync.aligned.m8n8.x4.shared.b16 {%0,%1,%2,%3}, [%4];" \
                 : "=r"(r0), "=r"(r1), "=r"(r2), "=r"(r3) : "r"(addr))

#define MMA_F16(c, a, b) \
    asm volatile( \
        "mma.sync.aligned.m16n8k16.row.col.f32.f16.f16.f32 " \
        "{%0,%1,%2,%3}, {%4,%5,%6,%7}, {%8,%9}, {%0,%1,%2,%3};" \
        : "+f"((c)[0]), "+f"((c)[1]), "+f"((c)[2]), "+f"((c)[3]) \
        : "r"((a)[0]), "r"((a)[1]), "r"((a)[2]), "r"((a)[3]), \
          "r"((b)[0]), "r"((b)[1]))

#define CP_ASYNC16(dst, src) \
    asm volatile("cp.async.cg.shared.global [%0], [%1], 16;" \
                 :: "r"(dst), "l"(src))
#define CP_COMMIT() asm volatile("cp.async.commit_group;" ::: "memory")
#define CP_WAIT0() asm volatile("cp.async.wait_group 0;" ::: "memory")
#define CP_WAIT1() asm volatile("cp.async.wait_group 1;" ::: "memory")

// split two floats into packed fp16x2 hi + fp16x2 lo (x -> low half)
__device__ __forceinline__ void split2h(float x, float y, uint32_t& h, uint32_t& l) {
    __half2 hh = __floats2half2_rn(x, y);
    float2 hf = __half22float2(hh);
    __half2 ll = __floats2half2_rn(x - hf.x, y - hf.y);
    h = *reinterpret_cast<uint32_t*>(&hh);
    l = *reinterpret_cast<uint32_t*>(&ll);
}

// ---------------------------------------------------------------------------
// Split kernels
// ---------------------------------------------------------------------------
__global__ void split_kernel(const float* __restrict__ in,
                             __half* __restrict__ hi,
                             __half* __restrict__ lo, int n) {
    int i = (blockIdx.x * blockDim.x + threadIdx.x) * 4;
    if (i >= n) return;
    float4 v = *(const float4*)(in + i);
    uint32_t h0, l0, h1, l1;
    split2h(v.x, v.y, h0, l0);
    split2h(v.z, v.w, h1, l1);
    *(uint32_t*)(hi + i) = h0;
    *(uint32_t*)(hi + i + 2) = h1;
    *(uint32_t*)(lo + i) = l0;
    *(uint32_t*)(lo + i + 2) = l1;
}

// W [1024, Ncols] -> W^T single fp16 [Ncols, 1024]
__global__ void wsplit_kernel(const float* __restrict__ W,
                              __half* __restrict__ out, int Ncols) {
    __shared__ float t[32][33];
    int n0 = blockIdx.x * 32, k0 = blockIdx.y * 32;
    int tx = threadIdx.x & 31, ty = threadIdx.x >> 5;  // 32 x 8
    #pragma unroll
    for (int r = 0; r < 32; r += 8)
        t[ty + r][tx] = W[(size_t)(k0 + ty + r) * Ncols + n0 + tx];
    __syncthreads();
    #pragma unroll
    for (int r = 0; r < 32; r += 8)
        out[(size_t)(n0 + ty + r) * 1024 + k0 + tx] = __float2half_rn(t[tx][ty + r]);
}

// ---------------------------------------------------------------------------
// mma.sync GEMM: C[M,N] = A[M,1024](hi+lo fp16) @ B[N,1024]^T(fp16) + bias
// 128x128 CTA tile, 8 warps (2x4 -> 64x32 warp tile), Kc=32 chunks,
// 2-stage cp.async pipeline (2 CTAs/SM), 2-pass accumulation.
// mode 0: row-major fp32 C store.
// mode 1: qkv epilogue -> q hi/lo (scaled 0.125), k single, v single (transp).
// ---------------------------------------------------------------------------
#define KCH 32
#define NCHUNK 32
#define TILEB (128 * 80)               // 10240 bytes per tile (80B rows)
#define STAGEB (3 * TILEB)             // Ahi, Alo, B = 30720
#define GEMM_SMEM (2 * STAGEB)         // 61440

__global__ __launch_bounds__(256, 2)
void mma_gemm(const __half* __restrict__ Ahi,
              const __half* __restrict__ Alo,
              const __half* __restrict__ Bm,
              const float* __restrict__ bias, float* __restrict__ C, int N,
              int mode,
              __half* __restrict__ qh_, __half* __restrict__ ql_,
              __half* __restrict__ k_, __half* __restrict__ v_) {
    extern __shared__ __align__(128) char smem[];
    const uint32_t smem_u32 = smem_to_u32(smem);
    const int tid = threadIdx.x;
    const int wid = tid >> 5;
    const int lane = tid & 31;
    const int wm = wid >> 2;
    const int wn = wid & 3;
    const int bn = blockIdx.x * 128;
    const int bm = blockIdx.y * 128;

    float acc[4][4][4];
    #pragma unroll
    for (int mt = 0; mt < 4; mt++)
        #pragma unroll
        for (int nt = 0; nt < 4; nt++)
            #pragma unroll
            for (int r = 0; r < 4; r++) acc[mt][nt][r] = 0.0f;

    auto load_stage = [&](int kc, int stage) {
        const int k0 = kc * KCH;
        const uint32_t sb = smem_u32 + stage * STAGEB;
        #pragma unroll
        for (int t = 0; t < 3; t++) {
            const __half* src = (t == 0) ? Ahi : (t == 1) ? Alo : Bm;
            const int rbase = (t < 2) ? bm : bn;
            #pragma unroll
            for (int s = 0; s < 2; s++) {
                int idx = s * 256 + tid;
                int row = idx >> 2;
                int c4 = idx & 3;
                const void* g = src + (size_t)(rbase + row) * 1024 + k0 + c4 * 8;
                uint32_t d = sb + t * TILEB + row * 80 + c4 * 16;
                CP_ASYNC16(d, g);
            }
        }
        CP_COMMIT();
    };

    load_stage(0, 0);
    load_stage(1, 1);

    const int amat = lane >> 3;
    const int rowin = lane & 7;
    const int am_base = wm * 64 + (amat & 1) * 8 + rowin;
    const int ak_base = (amat >> 1) * 8;
    const int bn_base = wn * 32 + ((lane >> 3) >> 1) * 8 + rowin;
    const int bk_base = ((lane >> 3) & 1) * 8;

    for (int kc = 0; kc < NCHUNK; kc++) {
        if (kc + 1 < NCHUNK) CP_WAIT1(); else CP_WAIT0();
        __syncthreads();

        const uint32_t sb = smem_u32 + (kc & 1) * STAGEB;
        #pragma unroll
        for (int ks = 0; ks < 2; ks++) {
            const int kb = ks * 16;
            uint32_t ah[4][4], al[4][4], bf[4][2];
            #pragma unroll
            for (int mt = 0; mt < 4; mt++) {
                uint32_t a = sb + (am_base + mt * 16) * 80 + (ak_base + kb) * 2;
                LDMATRIX_X4(ah[mt][0], ah[mt][1], ah[mt][2], ah[mt][3], a);
                LDMATRIX_X4(al[mt][0], al[mt][1], al[mt][2], al[mt][3], a + TILEB);
            }
            #pragma unroll
            for (int np = 0; np < 2; np++) {
                uint32_t b = sb + 2 * TILEB + (bn_base + np * 16) * 80 +
                             (bk_base + kb) * 2;
                LDMATRIX_X4(bf[np * 2][0], bf[np * 2][1],
                            bf[np * 2 + 1][0], bf[np * 2 + 1][1], b);
            }
            // 2-pass: A_hi*B then A_lo*B  (C = (A_hi+A_lo) * B exactly)
            #pragma unroll
            for (int mt = 0; mt < 4; mt++)
                #pragma unroll
                for (int nt = 0; nt < 4; nt++)
                    MMA_F16(acc[mt][nt], ah[mt], bf[nt]);
            #pragma unroll
            for (int mt = 0; mt < 4; mt++)
                #pragma unroll
                for (int nt = 0; nt < 4; nt++)
                    MMA_F16(acc[mt][nt], al[mt], bf[nt]);
        }
        __syncthreads();
        if (kc + 2 < NCHUNK) load_stage(kc + 2, kc & 1);
    }

    // ---- epilogue
    const int mrow = lane >> 2;
    const int ncol = (lane & 3) * 2;
    #pragma unroll
    for (int mt = 0; mt < 4; mt++) {
        #pragma unroll
        for (int nt = 0; nt < 4; nt++) {
            int n = bn + wn * 32 + nt * 8 + ncol;
            float2 bv = *(const float2*)(bias + n);
            #pragma unroll
            for (int half = 0; half < 2; half++) {
                int m = bm + wm * 64 + mt * 16 + mrow + half * 8;
                float2 v;
                v.x = acc[mt][nt][half * 2 + 0] + bv.x;
                v.y = acc[mt][nt][half * 2 + 1] + bv.y;
                if (mode == 0) {
                    *(float2*)(C + (size_t)m * N + n) = v;
                } else {
                    int which = n >> 10;
                    int rem = n & 1023;
                    int h = rem >> 6;
                    int d = rem & 63;
                    int b = m >> 11;
                    int l = m & 2047;
                    int bh = b * Hq + h;
                    if (which == 0) {
                        uint32_t h2, l2;
                        split2h(v.x * 0.125f, v.y * 0.125f, h2, l2);
                        size_t di = ((size_t)bh * Lq + l) * HDq + d;
                        *(uint32_t*)(qh_ + di) = h2;
                        *(uint32_t*)(ql_ + di) = l2;
                    } else if (which == 1) {
                        __half2 h2 = __floats2half2_rn(v.x, v.y);
                        size_t di = ((size_t)bh * Lq + l) * HDq + d;
                        *(__half2*)(k_ + di) = h2;
                    } else {
                        // v transposed single fp16: [bh][d][l]
                        size_t base = ((size_t)bh * HDq + d) * Lq + l;
                        v_[base] = __float2half_rn(v.x);
                        v_[base + Lq] = __float2half_rn(v.y);
                    }
                }
            }
        }
    }
}

// ---------------------------------------------------------------------------
// Flash attention (causal) on mma.sync fp16.
// S = (Q_hi+Q_lo) @ fl16(K)^T : 2-pass.  O += (P_hi+P_lo) @ fl16(V) : 2-pass.
// CTA: one (bh, 128-row q tile). 8 warps; warp w owns rows [w*16, w*16+16).
// Bc = 64 keys/iter, 2-stage cp.async on K/V (single fp16); V pre-transposed.
// Smem: Qhi 0 (18432), Qlo 18432; stage s at 36864 + s*18432:
//       K +0 (9216), V +9216 (rows padded to 144B).
// ---------------------------------------------------------------------------
#define AROWB 144
#define ATTN_SMEM 73728

__global__ __launch_bounds__(256, 2)
void attn_mma(const __half* __restrict__ qhi,
              const __half* __restrict__ qlo,
              const __half* __restrict__ kk_,
              const __half* __restrict__ vv_,
              __half* __restrict__ ohi,
              __half* __restrict__ olo) {
    extern __shared__ __align__(128) char smem[];
    const uint32_t su = smem_to_u32(smem);
    const int bh = blockIdx.y;
    const int qt = (int)gridDim.x - 1 - blockIdx.x;   // heavy tiles first
    const int q0 = qt * 128;
    const int tid = threadIdx.x;
    const int wid = tid >> 5;
    const int lane = tid & 31;
    const int r0 = wid * 16;
    const int rowin = lane & 7;
    const int g1 = (lane >> 3) & 1;
    const int g2 = (lane >> 3) >> 1;

    auto load_kv = [&](int kt2, int st) {
        const int k0 = kt2 * 64;
        const uint32_t sb = su + 36864 + st * 18432;
        #pragma unroll
        for (int s = 0; s < 2; s++) {
            int idx = s * 256 + tid;
            int row = idx >> 3;
            int c = idx & 7;
            const __half* gk = kk_ + ((size_t)bh * Lq + k0 + row) * HDq + c * 8;
            CP_ASYNC16(sb + row * AROWB + c * 16, gk);
            const __half* gv = vv_ + ((size_t)bh * HDq + row) * Lq + k0 + c * 8;
            CP_ASYNC16(sb + 9216 + row * AROWB + c * 16, gv);
        }
        CP_COMMIT();
    };

    // prologue: Q hi/lo + KV stage 0 in one group; KV stage 1 next
    #pragma unroll
    for (int s = 0; s < 4; s++) {
        int idx = s * 256 + tid;
        int row = idx >> 3;
        int c = idx & 7;
        const __half* gq = qhi + ((size_t)bh * Lq + q0 + row) * HDq + c * 8;
        CP_ASYNC16(su + row * AROWB + c * 16, gq);
        const __half* gq2 = qlo + ((size_t)bh * Lq + q0 + row) * HDq + c * 8;
        CP_ASYNC16(su + 18432 + row * AROWB + c * 16, gq2);
    }
    load_kv(0, 0);
    load_kv(1, 1);

    float oacc[8][4];
    #pragma unroll
    for (int nt = 0; nt < 8; nt++)
        #pragma unroll
        for (int r = 0; r < 4; r++) oacc[nt][r] = 0.0f;
    float mA = -1e30f, mB = -1e30f, lA = 0.0f, lB = 0.0f;

    const int nkt = 2 * qt + 2;
    for (int kt = 0; kt < nkt; kt++) {
        if (kt + 1 < nkt) CP_WAIT1(); else CP_WAIT0();
        __syncthreads();
        const uint32_t sb = su + 36864 + (kt & 1) * 18432;
        const int k0 = kt * 64;

        // ---- S = Q_hi@K^T + Q_lo@K^T  (rows r0..r0+15 x 64 keys)
        float sacc[8][4];
        #pragma unroll
        for (int nt = 0; nt < 8; nt++)
            #pragma unroll
            for (int r = 0; r < 4; r++) sacc[nt][r] = 0.0f;

        #pragma unroll
        for (int kk = 0; kk < 4; kk++) {
            uint32_t qhf[4], qlf[4];
            uint32_t qa = su + (r0 + g1 * 8 + rowin) * AROWB + (kk * 16 + g2 * 8) * 2;
            LDMATRIX_X4(qhf[0], qhf[1], qhf[2], qhf[3], qa);
            LDMATRIX_X4(qlf[0], qlf[1], qlf[2], qlf[3], qa + 18432);
            #pragma unroll
            for (int np = 0; np < 4; np++) {
                uint32_t kb[2][2];
                uint32_t ka = sb + (np * 16 + g2 * 8 + rowin) * AROWB +
                              (kk * 16 + g1 * 8) * 2;
                LDMATRIX_X4(kb[0][0], kb[0][1], kb[1][0], kb[1][1], ka);
                MMA_F16(sacc[np * 2],     qhf, kb[0]);
                MMA_F16(sacc[np * 2 + 1], qhf, kb[1]);
                MMA_F16(sacc[np * 2],     qlf, kb[0]);
                MMA_F16(sacc[np * 2 + 1], qlf, kb[1]);
            }
        }

        // ---- causal mask (only diagonal block: kt >= 2*qt)
        const int rA = q0 + r0 + (lane >> 2);
        if (kt >= 2 * qt) {
            #pragma unroll
            for (int nt = 0; nt < 8; nt++) {
                int c0 = k0 + nt * 8 + (lane & 3) * 2;
                if (c0 > rA) sacc[nt][0] = -1e30f;
                if (c0 + 1 > rA) sacc[nt][1] = -1e30f;
                if (c0 > rA + 8) sacc[nt][2] = -1e30f;
                if (c0 + 1 > rA + 8) sacc[nt][3] = -1e30f;
            }
        }

        // ---- online softmax (rows rA, rA+8 per lane; quad holds the 64 cols)
        float mxA = -1e30f, mxB = -1e30f;
        #pragma unroll
        for (int nt = 0; nt < 8; nt++) {
            mxA = fmaxf(mxA, fmaxf(sacc[nt][0], sacc[nt][1]));
            mxB = fmaxf(mxB, fmaxf(sacc[nt][2], sacc[nt][3]));
        }
        mxA = fmaxf(mxA, __shfl_xor_sync(0xffffffffu, mxA, 1));
        mxA = fmaxf(mxA, __shfl_xor_sync(0xffffffffu, mxA, 2));
        mxB = fmaxf(mxB, __shfl_xor_sync(0xffffffffu, mxB, 1));
        mxB = fmaxf(mxB, __shfl_xor_sync(0xffffffffu, mxB, 2));
        float mnA = fmaxf(mA, mxA);
        float mnB = fmaxf(mB, mxB);
        float aA = __expf(mA - mnA);
        float aB = __expf(mB - mnB);
        mA = mnA;
        mB = mnB;
        float lsA = 0.0f, lsB = 0.0f;
        #pragma unroll
        for (int nt = 0; nt < 8; nt++) {
            float p0 = __expf(sacc[nt][0] - mA);
            float p1 = __expf(sacc[nt][1] - mA);
            float p2 = __expf(sacc[nt][2] - mB);
            float p3 = __expf(sacc[nt][3] - mB);
            sacc[nt][0] = p0; sacc[nt][1] = p1;
            sacc[nt][2] = p2; sacc[nt][3] = p3;
            lsA += p0 + p1;
            lsB += p2 + p3;
        }
        lA = lA * aA + lsA;
        lB = lB * aB + lsB;
        #pragma unroll
        for (int nt = 0; nt < 8; nt++) {
            oacc[nt][0] *= aA; oacc[nt][1] *= aA;
            oacc[nt][2] *= aB; oacc[nt][3] *= aB;
        }

        // ---- PV: O += (P_hi + P_lo) @ V  (P from regs, V^T single in smem)
        #pragma unroll
        for (int kk2 = 0; kk2 < 4; kk2++) {
            const int t0 = kk2 * 2, t1 = t0 + 1;
            uint32_t ph[4], pl[4];
            split2h(sacc[t0][0], sacc[t0][1], ph[0], pl[0]);
            split2h(sacc[t0][2], sacc[t0][3], ph[1], pl[1]);
            split2h(sacc[t1][0], sacc[t1][1], ph[2], pl[2]);
            split2h(sacc[t1][2], sacc[t1][3], ph[3], pl[3]);
            #pragma unroll
            for (int np = 0; np < 4; np++) {
                uint32_t vb[2][2];
                uint32_t va = sb + 9216 + (np * 16 + g2 * 8 + rowin) * AROWB +
                              (kk2 * 16 + g1 * 8) * 2;
                LDMATRIX_X4(vb[0][0], vb[0][1], vb[1][0], vb[1][1], va);
                MMA_F16(oacc[np * 2],     ph, vb[0]);
                MMA_F16(oacc[np * 2 + 1], ph, vb[1]);
                MMA_F16(oacc[np * 2],     pl, vb[0]);
                MMA_F16(oacc[np * 2 + 1], pl, vb[1]);
            }
        }

        __syncthreads();
        if (kt + 2 < nkt) load_kv(kt + 2, kt & 1);
    }

    // ---- finalize: row-sum reduce over quad, normalize, store fp16 hi/lo
    lA += __shfl_xor_sync(0xffffffffu, lA, 1);
    lA += __shfl_xor_sync(0xffffffffu, lA, 2);
    lB += __shfl_xor_sync(0xffffffffu, lB, 1);
    lB += __shfl_xor_sync(0xffffffffu, lB, 2);
    float iA = 1.0f / lA;
    float iB = 1.0f / lB;

    const int b = bh >> 4;
    const int hh = bh & 15;
    const int rgA = q0 + r0 + (lane >> 2);
    #pragma unroll
    for (int nt = 0; nt < 8; nt++) {
        int d = nt * 8 + (lane & 3) * 2;
        size_t ia = ((size_t)(b * Lq + rgA)) * 1024 + hh * 64 + d;
        size_t ib = ((size_t)(b * Lq + rgA + 8)) * 1024 + hh * 64 + d;
        uint32_t h2, l2;
        split2h(oacc[nt][0] * iA, oacc[nt][1] * iA, h2, l2);
        *(uint32_t*)(ohi + ia) = h2;
        *(uint32_t*)(olo + ia) = l2;
        split2h(oacc[nt][2] * iB, oacc[nt][3] * iB, h2, l2);
        *(uint32_t*)(ohi + ib) = h2;
        *(uint32_t*)(olo + ib) = l2;
    }
}

// ---------------------------------------------------------------------------
// Launch
// ---------------------------------------------------------------------------
extern "C" void kernel_launch(void* const* d_in, const int* in_sizes, int n_in,
                              void* d_out, int out_size) {
    const float* x  = (const float*)d_in[0];
    const float* Wa = (const float*)d_in[1];
    const float* ba = (const float*)d_in[2];
    const float* Wp = (const float*)d_in[3];
    const float* bp = (const float*)d_in[4];
    float* out = (float*)d_out;

    __half *ahi, *alo, *wa, *wp, *qhi, *qlo, *kk, *vv;
    cudaGetSymbolAddress((void**)&ahi, g_ahi);
    cudaGetSymbolAddress((void**)&alo, g_alo);
    cudaGetSymbolAddress((void**)&wa, g_wa);
    cudaGetSymbolAddress((void**)&wp, g_wp);
    cudaGetSymbolAddress((void**)&qhi, g_qhi);
    cudaGetSymbolAddress((void**)&qlo, g_qlo);
    cudaGetSymbolAddress((void**)&kk, g_k);
    cudaGetSymbolAddress((void**)&vv, g_v);

    cudaFuncSetAttribute(mma_gemm, cudaFuncAttributeMaxDynamicSharedMemorySize,
                         GEMM_SMEM);
    cudaFuncSetAttribute(attn_mma, cudaFuncAttributeMaxDynamicSharedMemorySize,
                         ATTN_SMEM);

    // Split x to fp16 hi/lo; weights to single fp16 (transposed)
    split_kernel<<<8192, 256>>>(x, ahi, alo, 8192 * 1024);
    wsplit_kernel<<<dim3(96, 32), 256>>>(Wa, wa, 3072);
    wsplit_kernel<<<dim3(32, 32), 256>>>(Wp, wp, 1024);

    // 1) QKV projection -> q hi/lo (scaled), k single, v single (transposed)
    mma_gemm<<<dim3(24, 64), 256, GEMM_SMEM>>>(
        ahi, alo, wa, ba, nullptr, 3072, 1, qhi, qlo, kk, vv);

    // 2) causal flash attention -> o hi/lo into ahi/alo
    attn_mma<<<dim3(16, 64), 256, ATTN_SMEM>>>(qhi, qlo, kk, vv, ahi, alo);

    // 3) output projection
    mma_gemm<<<dim3(8, 64), 256, GEMM_SMEM>>>(
        ahi, alo, wp, bp, out, 1024, 0, nullptr, nullptr, nullptr, nullptr);
}

// round 17
// speedup vs baseline: 2.5112x; 1.6431x over previous
#include <cuda_runtime.h>
#include <cuda_fp16.h>
#include <cstdint>
#include <cstddef>

// ---------------------------------------------------------------------------
// Problem: B=4, L=2048, D=1024, H=16, Hd=64
//   qkv = x @ W_attn + b_attn            [8192 x 3072]
//   attn (causal, 16 heads, softmax)      -> o [8192 x 1024]
//   out = o @ W_proj + b_proj             [8192 x 1024]
// Round 17: full single fp16 operands everywhere (1-pass MMA in all three
// kernels). Error budget: R16 measured 2.6e-4 with B-side-only rounding;
// doubling rounding sources predicts ~4-5e-4, under the 1e-3 threshold.
// Mainloop skeleton identical to measured-best R9/R16 (KCH=32, 2-stage,
// 2 CTA/SM). tcgen05 unusable: harness PTX targets sm_103 (no 'a').
// ---------------------------------------------------------------------------

#define Bq 4
#define Lq 2048
#define Hq 16
#define HDq 64

// fp16 scratch
__device__ __half g_a[8192 * 1024];     // x / o (single fp16)
__device__ __half g_wa[3072 * 1024];    // W_attn^T single fp16
__device__ __half g_wp[1024 * 1024];    // W_proj^T single fp16
// q (pre-scaled 0.125); k; v TRANSPOSED [b,h,d,l] — all single fp16
__device__ __half g_q[64 * 2048 * 64];
__device__ __half g_k[64 * 2048 * 64];
__device__ __half g_v[64 * 64 * 2048];

__device__ __forceinline__ uint32_t smem_to_u32(const void* p) {
    uint32_t a;
    asm("{ .reg .u64 t; cvta.to.shared.u64 t, %1; cvt.u32.u64 %0, t; }"
        : "=r"(a) : "l"(p));
    return a;
}

#define LDMATRIX_X4(r0, r1, r2, r3, addr) \
    asm volatile("ldmatrix.sync.aligned.m8n8.x4.shared.b16 {%0,%1,%2,%3}, [%4];" \
                 : "=r"(r0), "=r"(r1), "=r"(r2), "=r"(r3) : "r"(addr))

#define MMA_F16(c, a, b) \
    asm volatile( \
        "mma.sync.aligned.m16n8k16.row.col.f32.f16.f16.f32 " \
        "{%0,%1,%2,%3}, {%4,%5,%6,%7}, {%8,%9}, {%0,%1,%2,%3};" \
        : "+f"((c)[0]), "+f"((c)[1]), "+f"((c)[2]), "+f"((c)[3]) \
        : "r"((a)[0]), "r"((a)[1]), "r"((a)[2]), "r"((a)[3]), \
          "r"((b)[0]), "r"((b)[1]))

#define CP_ASYNC16(dst, src) \
    asm volatile("cp.async.cg.shared.global [%0], [%1], 16;" \
                 :: "r"(dst), "l"(src))
#define CP_COMMIT() asm volatile("cp.async.commit_group;" ::: "memory")
#define CP_WAIT0() asm volatile("cp.async.wait_group 0;" ::: "memory")
#define CP_WAIT1() asm volatile("cp.async.wait_group 1;" ::: "memory")

__device__ __forceinline__ uint32_t pack_h2(float x, float y) {
    __half2 h = __floats2half2_rn(x, y);
    return *reinterpret_cast<uint32_t*>(&h);
}

// ---------------------------------------------------------------------------
// Convert kernels
// ---------------------------------------------------------------------------
__global__ void cvt_kernel(const float* __restrict__ in,
                           __half* __restrict__ out, int n) {
    int i = (blockIdx.x * blockDim.x + threadIdx.x) * 4;
    if (i >= n) return;
    float4 v = *(const float4*)(in + i);
    *(uint32_t*)(out + i) = pack_h2(v.x, v.y);
    *(uint32_t*)(out + i + 2) = pack_h2(v.z, v.w);
}

// W [1024, Ncols] -> W^T single fp16 [Ncols, 1024]
__global__ void wsplit_kernel(const float* __restrict__ W,
                              __half* __restrict__ out, int Ncols) {
    __shared__ float t[32][33];
    int n0 = blockIdx.x * 32, k0 = blockIdx.y * 32;
    int tx = threadIdx.x & 31, ty = threadIdx.x >> 5;  // 32 x 8
    #pragma unroll
    for (int r = 0; r < 32; r += 8)
        t[ty + r][tx] = W[(size_t)(k0 + ty + r) * Ncols + n0 + tx];
    __syncthreads();
    #pragma unroll
    for (int r = 0; r < 32; r += 8)
        out[(size_t)(n0 + ty + r) * 1024 + k0 + tx] = __float2half_rn(t[tx][ty + r]);
}

// ---------------------------------------------------------------------------
// mma.sync GEMM: C[M,N] = A[M,1024](fp16) @ B[N,1024]^T(fp16) + bias
// 128x128 CTA tile, 8 warps (2x4 -> 64x32 warp tile), Kc=32 chunks,
// 2-stage cp.async pipeline (2 CTAs/SM), 1-pass accumulation.
// mode 0: row-major fp32 C store.
// mode 1: qkv epilogue -> q (scaled 0.125), k, v (transposed), all fp16.
// ---------------------------------------------------------------------------
#define KCH 32
#define NCHUNK 32
#define TILEB (128 * 80)               // 10240 bytes per tile (80B rows)
#define STAGEB (2 * TILEB)             // A, B = 20480
#define GEMM_SMEM (2 * STAGEB)         // 40960

__global__ __launch_bounds__(256, 2)
void mma_gemm(const __half* __restrict__ Am,
              const __half* __restrict__ Bm,
              const float* __restrict__ bias, float* __restrict__ C, int N,
              int mode,
              __half* __restrict__ q_, __half* __restrict__ k_,
              __half* __restrict__ v_) {
    extern __shared__ __align__(128) char smem[];
    const uint32_t smem_u32 = smem_to_u32(smem);
    const int tid = threadIdx.x;
    const int wid = tid >> 5;
    const int lane = tid & 31;
    const int wm = wid >> 2;
    const int wn = wid & 3;
    const int bn = blockIdx.x * 128;
    const int bm = blockIdx.y * 128;

    float acc[4][4][4];
    #pragma unroll
    for (int mt = 0; mt < 4; mt++)
        #pragma unroll
        for (int nt = 0; nt < 4; nt++)
            #pragma unroll
            for (int r = 0; r < 4; r++) acc[mt][nt][r] = 0.0f;

    auto load_stage = [&](int kc, int stage) {
        const int k0 = kc * KCH;
        const uint32_t sb = smem_u32 + stage * STAGEB;
        #pragma unroll
        for (int t = 0; t < 2; t++) {
            const __half* src = (t == 0) ? Am : Bm;
            const int rbase = (t == 0) ? bm : bn;
            #pragma unroll
            for (int s = 0; s < 2; s++) {
                int idx = s * 256 + tid;
                int row = idx >> 2;
                int c4 = idx & 3;
                const void* g = src + (size_t)(rbase + row) * 1024 + k0 + c4 * 8;
                uint32_t d = sb + t * TILEB + row * 80 + c4 * 16;
                CP_ASYNC16(d, g);
            }
        }
        CP_COMMIT();
    };

    load_stage(0, 0);
    load_stage(1, 1);

    const int amat = lane >> 3;
    const int rowin = lane & 7;
    const int am_base = wm * 64 + (amat & 1) * 8 + rowin;
    const int ak_base = (amat >> 1) * 8;
    const int bn_base = wn * 32 + ((lane >> 3) >> 1) * 8 + rowin;
    const int bk_base = ((lane >> 3) & 1) * 8;

    for (int kc = 0; kc < NCHUNK; kc++) {
        if (kc + 1 < NCHUNK) CP_WAIT1(); else CP_WAIT0();
        __syncthreads();

        const uint32_t sb = smem_u32 + (kc & 1) * STAGEB;
        #pragma unroll
        for (int ks = 0; ks < 2; ks++) {
            const int kb = ks * 16;
            uint32_t ah[4][4], bf[4][2];
            #pragma unroll
            for (int mt = 0; mt < 4; mt++) {
                uint32_t a = sb + (am_base + mt * 16) * 80 + (ak_base + kb) * 2;
                LDMATRIX_X4(ah[mt][0], ah[mt][1], ah[mt][2], ah[mt][3], a);
            }
            #pragma unroll
            for (int np = 0; np < 2; np++) {
                uint32_t b = sb + TILEB + (bn_base + np * 16) * 80 +
                             (bk_base + kb) * 2;
                LDMATRIX_X4(bf[np * 2][0], bf[np * 2][1],
                            bf[np * 2 + 1][0], bf[np * 2 + 1][1], b);
            }
            #pragma unroll
            for (int mt = 0; mt < 4; mt++)
                #pragma unroll
                for (int nt = 0; nt < 4; nt++)
                    MMA_F16(acc[mt][nt], ah[mt], bf[nt]);
        }
        __syncthreads();
        if (kc + 2 < NCHUNK) load_stage(kc + 2, kc & 1);
    }

    // ---- epilogue
    const int mrow = lane >> 2;
    const int ncol = (lane & 3) * 2;
    #pragma unroll
    for (int mt = 0; mt < 4; mt++) {
        #pragma unroll
        for (int nt = 0; nt < 4; nt++) {
            int n = bn + wn * 32 + nt * 8 + ncol;
            float2 bv = *(const float2*)(bias + n);
            #pragma unroll
            for (int half = 0; half < 2; half++) {
                int m = bm + wm * 64 + mt * 16 + mrow + half * 8;
                float2 v;
                v.x = acc[mt][nt][half * 2 + 0] + bv.x;
                v.y = acc[mt][nt][half * 2 + 1] + bv.y;
                if (mode == 0) {
                    *(float2*)(C + (size_t)m * N + n) = v;
                } else {
                    int which = n >> 10;
                    int rem = n & 1023;
                    int h = rem >> 6;
                    int d = rem & 63;
                    int b = m >> 11;
                    int l = m & 2047;
                    int bh = b * Hq + h;
                    if (which == 0) {
                        size_t di = ((size_t)bh * Lq + l) * HDq + d;
                        *(uint32_t*)(q_ + di) = pack_h2(v.x * 0.125f, v.y * 0.125f);
                    } else if (which == 1) {
                        size_t di = ((size_t)bh * Lq + l) * HDq + d;
                        *(uint32_t*)(k_ + di) = pack_h2(v.x, v.y);
                    } else {
                        // v transposed single fp16: [bh][d][l]
                        size_t base = ((size_t)bh * HDq + d) * Lq + l;
                        v_[base] = __float2half_rn(v.x);
                        v_[base + Lq] = __float2half_rn(v.y);
                    }
                }
            }
        }
    }
}

// ---------------------------------------------------------------------------
// Flash attention (causal) on mma.sync fp16, single-pass S and PV.
// CTA: one (bh, 128-row q tile). 8 warps; warp w owns rows [w*16, w*16+16).
// Bc = 64 keys/iter, 2-stage cp.async on K/V; V pre-transposed.
// Smem: Q 0 (18432); stage s at 18432 + s*18432: K +0 (9216), V +9216.
// Rows padded to 144B. Total 55296.
// ---------------------------------------------------------------------------
#define AROWB 144
#define ATTN_SMEM 55296

__global__ __launch_bounds__(256, 2)
void attn_mma(const __half* __restrict__ qq_,
              const __half* __restrict__ kk_,
              const __half* __restrict__ vv_,
              __half* __restrict__ o_) {
    extern __shared__ __align__(128) char smem[];
    const uint32_t su = smem_to_u32(smem);
    const int bh = blockIdx.y;
    const int qt = (int)gridDim.x - 1 - blockIdx.x;   // heavy tiles first
    const int q0 = qt * 128;
    const int tid = threadIdx.x;
    const int wid = tid >> 5;
    const int lane = tid & 31;
    const int r0 = wid * 16;
    const int rowin = lane & 7;
    const int g1 = (lane >> 3) & 1;
    const int g2 = (lane >> 3) >> 1;

    auto load_kv = [&](int kt2, int st) {
        const int k0 = kt2 * 64;
        const uint32_t sb = su + 18432 + st * 18432;
        #pragma unroll
        for (int s = 0; s < 2; s++) {
            int idx = s * 256 + tid;
            int row = idx >> 3;
            int c = idx & 7;
            const __half* gk = kk_ + ((size_t)bh * Lq + k0 + row) * HDq + c * 8;
            CP_ASYNC16(sb + row * AROWB + c * 16, gk);
            const __half* gv = vv_ + ((size_t)bh * HDq + row) * Lq + k0 + c * 8;
            CP_ASYNC16(sb + 9216 + row * AROWB + c * 16, gv);
        }
        CP_COMMIT();
    };

    // prologue: Q + KV stage 0 in one group; KV stage 1 next
    #pragma unroll
    for (int s = 0; s < 4; s++) {
        int idx = s * 256 + tid;
        int row = idx >> 3;
        int c = idx & 7;
        const __half* gq = qq_ + ((size_t)bh * Lq + q0 + row) * HDq + c * 8;
        CP_ASYNC16(su + row * AROWB + c * 16, gq);
    }
    load_kv(0, 0);
    load_kv(1, 1);

    float oacc[8][4];
    #pragma unroll
    for (int nt = 0; nt < 8; nt++)
        #pragma unroll
        for (int r = 0; r < 4; r++) oacc[nt][r] = 0.0f;
    float mA = -1e30f, mB = -1e30f, lA = 0.0f, lB = 0.0f;

    const int nkt = 2 * qt + 2;
    for (int kt = 0; kt < nkt; kt++) {
        if (kt + 1 < nkt) CP_WAIT1(); else CP_WAIT0();
        __syncthreads();
        const uint32_t sb = su + 18432 + (kt & 1) * 18432;
        const int k0 = kt * 64;

        // ---- S = Q @ K^T  (rows r0..r0+15 x 64 keys)
        float sacc[8][4];
        #pragma unroll
        for (int nt = 0; nt < 8; nt++)
            #pragma unroll
            for (int r = 0; r < 4; r++) sacc[nt][r] = 0.0f;

        #pragma unroll
        for (int kk = 0; kk < 4; kk++) {
            uint32_t qf[4];
            uint32_t qa = su + (r0 + g1 * 8 + rowin) * AROWB + (kk * 16 + g2 * 8) * 2;
            LDMATRIX_X4(qf[0], qf[1], qf[2], qf[3], qa);
            #pragma unroll
            for (int np = 0; np < 4; np++) {
                uint32_t kb[2][2];
                uint32_t ka = sb + (np * 16 + g2 * 8 + rowin) * AROWB +
                              (kk * 16 + g1 * 8) * 2;
                LDMATRIX_X4(kb[0][0], kb[0][1], kb[1][0], kb[1][1], ka);
                MMA_F16(sacc[np * 2],     qf, kb[0]);
                MMA_F16(sacc[np * 2 + 1], qf, kb[1]);
            }
        }

        // ---- causal mask (only diagonal block: kt >= 2*qt)
        const int rA = q0 + r0 + (lane >> 2);
        if (kt >= 2 * qt) {
            #pragma unroll
            for (int nt = 0; nt < 8; nt++) {
                int c0 = k0 + nt * 8 + (lane & 3) * 2;
                if (c0 > rA) sacc[nt][0] = -1e30f;
                if (c0 + 1 > rA) sacc[nt][1] = -1e30f;
                if (c0 > rA + 8) sacc[nt][2] = -1e30f;
                if (c0 + 1 > rA + 8) sacc[nt][3] = -1e30f;
            }
        }

        // ---- online softmax (rows rA, rA+8 per lane; quad holds the 64 cols)
        float mxA = -1e30f, mxB = -1e30f;
        #pragma unroll
        for (int nt = 0; nt < 8; nt++) {
            mxA = fmaxf(mxA, fmaxf(sacc[nt][0], sacc[nt][1]));
            mxB = fmaxf(mxB, fmaxf(sacc[nt][2], sacc[nt][3]));
        }
        mxA = fmaxf(mxA, __shfl_xor_sync(0xffffffffu, mxA, 1));
        mxA = fmaxf(mxA, __shfl_xor_sync(0xffffffffu, mxA, 2));
        mxB = fmaxf(mxB, __shfl_xor_sync(0xffffffffu, mxB, 1));
        mxB = fmaxf(mxB, __shfl_xor_sync(0xffffffffu, mxB, 2));
        float mnA = fmaxf(mA, mxA);
        float mnB = fmaxf(mB, mxB);
        float aA = __expf(mA - mnA);
        float aB = __expf(mB - mnB);
        mA = mnA;
        mB = mnB;
        float lsA = 0.0f, lsB = 0.0f;
        #pragma unroll
        for (int nt = 0; nt < 8; nt++) {
            float p0 = __expf(sacc[nt][0] - mA);
            float p1 = __expf(sacc[nt][1] - mA);
            float p2 = __expf(sacc[nt][2] - mB);
            float p3 = __expf(sacc[nt][3] - mB);
            sacc[nt][0] = p0; sacc[nt][1] = p1;
            sacc[nt][2] = p2; sacc[nt][3] = p3;
            lsA += p0 + p1;
            lsB += p2 + p3;
        }
        lA = lA * aA + lsA;
        lB = lB * aB + lsB;
        #pragma unroll
        for (int nt = 0; nt < 8; nt++) {
            oacc[nt][0] *= aA; oacc[nt][1] *= aA;
            oacc[nt][2] *= aB; oacc[nt][3] *= aB;
        }

        // ---- PV: O += P @ V  (P fp16 from regs, V^T in smem)
        #pragma unroll
        for (int kk2 = 0; kk2 < 4; kk2++) {
            const int t0 = kk2 * 2, t1 = t0 + 1;
            uint32_t ph[4];
            ph[0] = pack_h2(sacc[t0][0], sacc[t0][1]);
            ph[1] = pack_h2(sacc[t0][2], sacc[t0][3]);
            ph[2] = pack_h2(sacc[t1][0], sacc[t1][1]);
            ph[3] = pack_h2(sacc[t1][2], sacc[t1][3]);
            #pragma unroll
            for (int np = 0; np < 4; np++) {
                uint32_t vb[2][2];
                uint32_t va = sb + 9216 + (np * 16 + g2 * 8 + rowin) * AROWB +
                              (kk2 * 16 + g1 * 8) * 2;
                LDMATRIX_X4(vb[0][0], vb[0][1], vb[1][0], vb[1][1], va);
                MMA_F16(oacc[np * 2],     ph, vb[0]);
                MMA_F16(oacc[np * 2 + 1], ph, vb[1]);
            }
        }

        __syncthreads();
        if (kt + 2 < nkt) load_kv(kt + 2, kt & 1);
    }

    // ---- finalize: row-sum reduce over quad, normalize, store fp16
    lA += __shfl_xor_sync(0xffffffffu, lA, 1);
    lA += __shfl_xor_sync(0xffffffffu, lA, 2);
    lB += __shfl_xor_sync(0xffffffffu, lB, 1);
    lB += __shfl_xor_sync(0xffffffffu, lB, 2);
    float iA = 1.0f / lA;
    float iB = 1.0f / lB;

    const int b = bh >> 4;
    const int hh = bh & 15;
    const int rgA = q0 + r0 + (lane >> 2);
    #pragma unroll
    for (int nt = 0; nt < 8; nt++) {
        int d = nt * 8 + (lane & 3) * 2;
        size_t ia = ((size_t)(b * Lq + rgA)) * 1024 + hh * 64 + d;
        size_t ib = ((size_t)(b * Lq + rgA + 8)) * 1024 + hh * 64 + d;
        *(uint32_t*)(o_ + ia) = pack_h2(oacc[nt][0] * iA, oacc[nt][1] * iA);
        *(uint32_t*)(o_ + ib) = pack_h2(oacc[nt][2] * iB, oacc[nt][3] * iB);
    }
}

// ---------------------------------------------------------------------------
// Launch
// ---------------------------------------------------------------------------
extern "C" void kernel_launch(void* const* d_in, const int* in_sizes, int n_in,
                              void* d_out, int out_size) {
    const float* x  = (const float*)d_in[0];
    const float* Wa = (const float*)d_in[1];
    const float* ba = (const float*)d_in[2];
    const float* Wp = (const float*)d_in[3];
    const float* bp = (const float*)d_in[4];
    float* out = (float*)d_out;

    __half *a_, *wa, *wp, *q_, *k_, *v_;
    cudaGetSymbolAddress((void**)&a_, g_a);
    cudaGetSymbolAddress((void**)&wa, g_wa);
    cudaGetSymbolAddress((void**)&wp, g_wp);
    cudaGetSymbolAddress((void**)&q_, g_q);
    cudaGetSymbolAddress((void**)&k_, g_k);
    cudaGetSymbolAddress((void**)&v_, g_v);

    cudaFuncSetAttribute(mma_gemm, cudaFuncAttributeMaxDynamicSharedMemorySize,
                         GEMM_SMEM);
    cudaFuncSetAttribute(attn_mma, cudaFuncAttributeMaxDynamicSharedMemorySize,
                         ATTN_SMEM);

    // Convert x to fp16; weights to single fp16 (transposed)
    cvt_kernel<<<8192, 256>>>(x, a_, 8192 * 1024);
    wsplit_kernel<<<dim3(96, 32), 256>>>(Wa, wa, 3072);
    wsplit_kernel<<<dim3(32, 32), 256>>>(Wp, wp, 1024);

    // 1) QKV projection -> q (scaled), k, v (transposed), all fp16
    mma_gemm<<<dim3(24, 64), 256, GEMM_SMEM>>>(
        a_, wa, ba, nullptr, 3072, 1, q_, k_, v_);

    // 2) causal flash attention -> o fp16 into a_
    attn_mma<<<dim3(16, 64), 256, ATTN_SMEM>>>(q_, k_, v_, a_);

    // 3) output projection
    mma_gemm<<<dim3(8, 64), 256, GEMM_SMEM>>>(
        a_, wp, bp, out, 1024, 0, nullptr, nullptr, nullptr);
}